// round 14
// baseline (speedup 1.0000x reference)
#include <cuda_runtime.h>
#include <cuda_fp16.h>
#include <cstdint>
#include <math.h>

// Problem constants
#define BB 8
#define NN 1024
#define DD 768
#define HH 12
#define YY 64
#define MM 3072
#define STEPS 12
#define ALPHA 0.1f
#define EPS_LN 1e-5f
#define BETA_ATT 0.125f   // 1/sqrt(64)

#define BN_TOK (BB*NN)             // 8192
#define GSZ    (BB*NN*DD)          // 6291456
#define RSZ    (BB*NN*MM)          // 25165824

// Scratch (static __device__ arrays: sanctioned alloc-free workaround)
__device__ __half d_g[GSZ];
__device__ __half d_q[GSZ];
__device__ __half d_k[GSZ];
__device__ __half d_dq[GSZ];
__device__ __half d_dk[GSZ];
__device__ __half d_r[RSZ];
__device__ float  d_acc[GSZ];
__device__ float  d_lse[BB*HH*NN];
__device__ __half d_wqh[DD*DD];
__device__ __half d_wkh[DD*DD];
__device__ __half d_xih[MM*DD];
__device__ __half d_wqT[DD*DD];
__device__ __half d_wkT[DD*DD];
__device__ __half d_xiT[DD*MM];

// ===========================================================================
// helpers
// ===========================================================================
__device__ __forceinline__ uint32_t smem_u32(const void* p) {
    uint32_t a;
    asm("{ .reg .u64 t; cvta.to.shared.u64 t, %1; cvt.u32.u64 %0, t; }"
        : "=r"(a) : "l"(p));
    return a;
}
__device__ __forceinline__ void mma_fp16(float* c, const uint32_t* a, const uint32_t* b) {
    asm volatile(
        "mma.sync.aligned.m16n8k16.row.col.f32.f16.f16.f32 "
        "{%0,%1,%2,%3}, {%4,%5,%6,%7}, {%8,%9}, {%0,%1,%2,%3};"
        : "+f"(c[0]), "+f"(c[1]), "+f"(c[2]), "+f"(c[3])
        : "r"(a[0]), "r"(a[1]), "r"(a[2]), "r"(a[3]), "r"(b[0]), "r"(b[1]));
}
__device__ __forceinline__ void ldsm_x4(uint32_t& r0, uint32_t& r1, uint32_t& r2,
                                        uint32_t& r3, uint32_t addr) {
    asm volatile("ldmatrix.sync.aligned.m8n8.x4.shared.b16 {%0,%1,%2,%3}, [%4];"
        : "=r"(r0), "=r"(r1), "=r"(r2), "=r"(r3) : "r"(addr));
}
__device__ __forceinline__ void ldsm_x4_t(uint32_t& r0, uint32_t& r1, uint32_t& r2,
                                          uint32_t& r3, uint32_t addr) {
    asm volatile("ldmatrix.sync.aligned.m8n8.x4.trans.shared.b16 {%0,%1,%2,%3}, [%4];"
        : "=r"(r0), "=r"(r1), "=r"(r2), "=r"(r3) : "r"(addr));
}
__device__ __forceinline__ void cp_async16(uint32_t dst, const void* src) {
    asm volatile("cp.async.cg.shared.global [%0], [%1], 16;" :: "r"(dst), "l"(src));
}
#define CP_COMMIT() asm volatile("cp.async.commit_group;" ::: "memory")
#define CP_WAIT1()  asm volatile("cp.async.wait_group 1;" ::: "memory")
#define CP_WAIT2()  asm volatile("cp.async.wait_group 2;" ::: "memory")

#define HP 72      // halves per smem row (144B: 16B-aligned, LDSM conflict-free)
#define QP 72      // fp16 pitch, flash tiles

// ===========================================================================
// Generic fp16 GEMM: 128x256 block tile, 8 warps (2x4) x warp 64x64,
// ldmatrix fragments, cp.async 3-stage pipeline, K-chunk 64.
//   C[m,n] = (accum?C:0) + scale * sum_k A[m][k]*B[n][k]   (+relu)
//   OH=1: C is __half;  OH=0: C is float.
// ===========================================================================
template<int R>
__device__ __forceinline__ void stageH(uint32_t dstu, const __half* __restrict__ src,
                                       int r0, int k0, long ld, int t)
{
#pragma unroll
    for (int p = 0; p < R / 32; p++) {
        int c = t + p * 256;
        int i = c >> 3, jc = c & 7;
        cp_async16(dstu + (uint32_t)(i * HP + 8 * jc) * 2,
                   src + (long)(r0 + i) * ld + k0 + 8 * jc);
    }
}

template<int OH>
__global__ __launch_bounds__(256, 1)
void hgemm(const __half* __restrict__ A, const __half* __restrict__ B,
           void* __restrict__ Cv, int Kdim, long lda, long ldb, long ldc,
           float scale, int relu, int accum)
{
    extern __shared__ __half sh[];
    constexpr int AW = 128 * HP;            // halves per A stage
    constexpr int BW = 256 * HP;            // halves per B stage
    const uint32_t smu = smem_u32(sh);
    uint32_t Au[3], Bu[3];
#pragma unroll
    for (int s = 0; s < 3; s++) {
        Au[s] = smu + (uint32_t)(s * (AW + BW)) * 2;
        Bu[s] = Au[s] + AW * 2;
    }

    const int t = threadIdx.x, lane = t & 31, wid = t >> 5;
    const int wm = wid & 1, wn = wid >> 1;      // 2 x 4 warps; warp tile 64x64
    const int qr = lane >> 2, qc = lane & 3;
    const int grp = lane >> 3, row = lane & 7;
    const int m0 = blockIdx.y * 128;
    const int n0 = blockIdx.x * 256;

    // ldmatrix per-lane byte offsets (within a stage)
    uint32_t aoff[4], boff[4];
#pragma unroll
    for (int mt = 0; mt < 4; mt++)
        aoff[mt] = (uint32_t)(((wm * 64 + mt * 16 + ((grp & 1) << 3) + row) * HP
                             + ((grp >> 1) << 3)) * 2);
#pragma unroll
    for (int p = 0; p < 4; p++)
        boff[p] = (uint32_t)(((wn * 64 + (2 * p + (grp >> 1)) * 8 + row) * HP
                             + ((grp & 1) << 3)) * 2);

    float acc[4][8][4];
#pragma unroll
    for (int i = 0; i < 4; i++)
#pragma unroll
        for (int j = 0; j < 8; j++)
#pragma unroll
            for (int e = 0; e < 4; e++) acc[i][j][e] = 0.f;

    const int CH = Kdim >> 6;

    // prologue: stage chunks 0 and 1
    stageH<128>(Au[0], A, m0, 0, lda, t);
    stageH<256>(Bu[0], B, n0, 0, ldb, t);
    CP_COMMIT();
    if (CH > 1) {
        stageH<128>(Au[1], A, m0, 64, lda, t);
        stageH<256>(Bu[1], B, n0, 64, ldb, t);
    }
    CP_COMMIT();

    for (int c = 0; c < CH; c++) {
        const int buf = c % 3;
        if (c + 2 < CH) {
            const int nb = (c + 2) % 3;
            stageH<128>(Au[nb], A, m0, (c + 2) * 64, lda, t);
            stageH<256>(Bu[nb], B, n0, (c + 2) * 64, ldb, t);
        }
        CP_COMMIT();
        CP_WAIT2();              // chunk c resident
        __syncthreads();

#pragma unroll
        for (int ks = 0; ks < 4; ks++) {
            uint32_t af[4][4], bf[8][2];
#pragma unroll
            for (int mt = 0; mt < 4; mt++)
                ldsm_x4(af[mt][0], af[mt][1], af[mt][2], af[mt][3],
                        Au[buf] + aoff[mt] + ks * 32);
#pragma unroll
            for (int p = 0; p < 4; p++)
                ldsm_x4(bf[2 * p][0], bf[2 * p][1], bf[2 * p + 1][0], bf[2 * p + 1][1],
                        Bu[buf] + boff[p] + ks * 32);
#pragma unroll
            for (int mt = 0; mt < 4; mt++)
#pragma unroll
                for (int nt = 0; nt < 8; nt++)
                    mma_fp16(acc[mt][nt], af[mt], bf[nt]);
        }
        __syncthreads();         // stage (c+3) reuses this buffer next iter
    }

#pragma unroll
    for (int mt = 0; mt < 4; mt++) {
        int rw = m0 + wm * 64 + mt * 16 + qr;
#pragma unroll
        for (int nt = 0; nt < 8; nt++) {
            int col = n0 + wn * 64 + nt * 8 + (qc << 1);
#pragma unroll
            for (int h = 0; h < 2; h++) {
                long idx = (long)(rw + 8 * h) * ldc + col;
                float v0 = acc[mt][nt][2 * h + 0] * scale;
                float v1 = acc[mt][nt][2 * h + 1] * scale;
                if (relu) { v0 = fmaxf(v0, 0.f); v1 = fmaxf(v1, 0.f); }
                if (OH) {
                    __half2 w = __floats2half2_rn(v0, v1);
                    *(uint32_t*)&((__half*)Cv)[idx] = *(uint32_t*)&w;
                } else {
                    float* C = (float*)Cv;
                    if (accum) {
                        float2 o = *(const float2*)&C[idx];
                        v0 += o.x; v1 += o.y;
                    }
                    float2 w; w.x = v0; w.y = v1;
                    *(float2*)&C[idx] = w;
                }
            }
        }
    }
}

// ===========================================================================
// Flash attention gradients: ldmatrix (+trans) fragments, cp.async K/Q chunks.
// ===========================================================================
__global__ __launch_bounds__(256, 2)
void dq_flash(const __half* __restrict__ qg, const __half* __restrict__ kg,
              __half* __restrict__ dqg, float* __restrict__ lse)
{
    __shared__ __half Qs[128 * QP];
    __shared__ __half Ka[2][64 * QP];

    const int t = threadIdx.x, lane = t & 31, w = t >> 5;
    const int qr = lane >> 2, qc = lane & 3;
    const int grp = lane >> 3, row = lane & 7;
    const int q0 = blockIdx.x * 128;
    const int bh = blockIdx.y;
    const int b = bh / HH, h = bh % HH;
    const __half* qb = qg + (long)b * NN * DD + h * YY;
    const __half* kb = kg + (long)b * NN * DD + h * YY;
    __half* dqb = dqg + (long)b * NN * DD + h * YY;

    const uint32_t Qsu = smem_u32(Qs);
    const uint32_t Kau[2] = { smem_u32(Ka[0]), smem_u32(Ka[1]) };

    const uint32_t qoff = (uint32_t)(((w * 16 + ((grp & 1) << 3) + row) * QP
                                    + ((grp >> 1) << 3)) * 2);
    uint32_t soff[4], toff[4];
#pragma unroll
    for (int p = 0; p < 4; p++) {
        soff[p] = (uint32_t)((((2 * p + (grp >> 1)) * 8 + row) * QP
                             + ((grp & 1) << 3)) * 2);
        toff[p] = (uint32_t)(((((grp & 1) << 3) + row) * QP
                             + (2 * p + (grp >> 1)) * 8) * 2);
    }

#pragma unroll
    for (int p = 0; p < 4; p++) {
        int c = t + p * 256;
        int i = c >> 3, jc = c & 7;
        cp_async16(Qsu + (uint32_t)(i * QP + 8 * jc) * 2,
                   qb + (long)(q0 + i) * DD + 8 * jc);
    }
#pragma unroll
    for (int p = 0; p < 2; p++) {
        int c = t + p * 256;
        int i = c >> 3, jc = c & 7;
        cp_async16(Kau[0] + (uint32_t)(i * QP + 8 * jc) * 2,
                   kb + (long)i * DD + 8 * jc);
    }
    CP_COMMIT();

    float m0 = -1e30f, m1 = -1e30f, l0 = 0.f, l1 = 0.f;
    float dqa[8][4];
#pragma unroll
    for (int i = 0; i < 8; i++)
#pragma unroll
        for (int e = 0; e < 4; e++) dqa[i][e] = 0.f;

    for (int c = 0; c < 16; c++) {
        const int buf = c & 1;
        if (c + 1 < 16) {
#pragma unroll
            for (int p = 0; p < 2; p++) {
                int cc = t + p * 256;
                int i = cc >> 3, jc = cc & 7;
                cp_async16(Kau[buf ^ 1] + (uint32_t)(i * QP + 8 * jc) * 2,
                           kb + (long)((c + 1) * 64 + i) * DD + 8 * jc);
            }
        }
        CP_COMMIT();
        CP_WAIT1();
        __syncthreads();

        float s[8][4];
#pragma unroll
        for (int i = 0; i < 8; i++)
#pragma unroll
            for (int e = 0; e < 4; e++) s[i][e] = 0.f;
#pragma unroll
        for (int kc = 0; kc < 4; kc++) {
            uint32_t a[4], bf[8][2];
            ldsm_x4(a[0], a[1], a[2], a[3], Qsu + qoff + kc * 32);
#pragma unroll
            for (int p = 0; p < 4; p++)
                ldsm_x4(bf[2 * p][0], bf[2 * p][1], bf[2 * p + 1][0], bf[2 * p + 1][1],
                        Kau[buf] + soff[p] + kc * 32);
#pragma unroll
            for (int nt = 0; nt < 8; nt++)
                mma_fp16(s[nt], a, bf[nt]);
        }
#pragma unroll
        for (int nt = 0; nt < 8; nt++)
#pragma unroll
            for (int e = 0; e < 4; e++) s[nt][e] *= BETA_ATT;

        float bm0 = -1e30f, bm1 = -1e30f;
#pragma unroll
        for (int nt = 0; nt < 8; nt++) {
            bm0 = fmaxf(bm0, fmaxf(s[nt][0], s[nt][1]));
            bm1 = fmaxf(bm1, fmaxf(s[nt][2], s[nt][3]));
        }
        bm0 = fmaxf(bm0, __shfl_xor_sync(0xffffffffu, bm0, 1));
        bm0 = fmaxf(bm0, __shfl_xor_sync(0xffffffffu, bm0, 2));
        bm1 = fmaxf(bm1, __shfl_xor_sync(0xffffffffu, bm1, 1));
        bm1 = fmaxf(bm1, __shfl_xor_sync(0xffffffffu, bm1, 2));
        float mn0 = fmaxf(m0, bm0), mn1 = fmaxf(m1, bm1);
        float rs0 = __expf(m0 - mn0), rs1 = __expf(m1 - mn1);
        m0 = mn0; m1 = mn1;

        uint32_t Pf[8][2];
        float lp0 = 0.f, lp1 = 0.f;
#pragma unroll
        for (int nt = 0; nt < 8; nt++) {
            float p0 = __expf(s[nt][0] - m0), p1 = __expf(s[nt][1] - m0);
            float p2 = __expf(s[nt][2] - m1), p3 = __expf(s[nt][3] - m1);
            lp0 += p0 + p1; lp1 += p2 + p3;
            __half2 x = __floats2half2_rn(p0, p1); Pf[nt][0] = *(uint32_t*)&x;
            __half2 y = __floats2half2_rn(p2, p3); Pf[nt][1] = *(uint32_t*)&y;
        }
        l0 = l0 * rs0 + lp0; l1 = l1 * rs1 + lp1;
#pragma unroll
        for (int nt = 0; nt < 8; nt++) {
            dqa[nt][0] *= rs0; dqa[nt][1] *= rs0;
            dqa[nt][2] *= rs1; dqa[nt][3] *= rs1;
        }

#pragma unroll
        for (int kc = 0; kc < 4; kc++) {
            uint32_t a[4] = { Pf[2 * kc][0], Pf[2 * kc][1],
                              Pf[2 * kc + 1][0], Pf[2 * kc + 1][1] };
            uint32_t bf[8][2];
#pragma unroll
            for (int p = 0; p < 4; p++)
                ldsm_x4_t(bf[2 * p][0], bf[2 * p][1], bf[2 * p + 1][0], bf[2 * p + 1][1],
                          Kau[buf] + toff[p] + (uint32_t)(kc * 16 * QP * 2));
#pragma unroll
            for (int nt = 0; nt < 8; nt++)
                mma_fp16(dqa[nt], a, bf[nt]);
        }
        __syncthreads();
    }

    l0 += __shfl_xor_sync(0xffffffffu, l0, 1);
    l0 += __shfl_xor_sync(0xffffffffu, l0, 2);
    l1 += __shfl_xor_sync(0xffffffffu, l1, 1);
    l1 += __shfl_xor_sync(0xffffffffu, l1, 2);
    const float li0 = 1.f / l0, li1 = 1.f / l1;

    const int r0 = q0 + w * 16 + qr;
#pragma unroll
    for (int nt = 0; nt < 8; nt++) {
        int col = nt * 8 + 2 * qc;
        __half2 v0 = __floats2half2_rn(dqa[nt][0] * li0, dqa[nt][1] * li0);
        __half2 v1 = __floats2half2_rn(dqa[nt][2] * li1, dqa[nt][3] * li1);
        *(uint32_t*)(dqb + (long)r0 * DD + col) = *(uint32_t*)&v0;
        *(uint32_t*)(dqb + (long)(r0 + 8) * DD + col) = *(uint32_t*)&v1;
    }
    if (qc == 0) {
        lse[(long)bh * NN + r0]     = m0 + logf(l0);
        lse[(long)bh * NN + r0 + 8] = m1 + logf(l1);
    }
}

__global__ __launch_bounds__(256, 2)
void dk_flash(const __half* __restrict__ qg, const __half* __restrict__ kg,
              __half* __restrict__ dkg, const float* __restrict__ lse)
{
    __shared__ __half Ks[128 * QP];
    __shared__ __half Qa[2][64 * QP];
    __shared__ float sL[64];

    const int t = threadIdx.x, lane = t & 31, w = t >> 5;
    const int qr = lane >> 2, qc = lane & 3;
    const int grp = lane >> 3, row = lane & 7;
    const int k0 = blockIdx.x * 128;
    const int bh = blockIdx.y;
    const int b = bh / HH, h = bh % HH;
    const __half* qb = qg + (long)b * NN * DD + h * YY;
    const __half* kb = kg + (long)b * NN * DD + h * YY;
    __half* dkb = dkg + (long)b * NN * DD + h * YY;

    const uint32_t Ksu = smem_u32(Ks);
    const uint32_t Qau[2] = { smem_u32(Qa[0]), smem_u32(Qa[1]) };

    const uint32_t koff = (uint32_t)(((w * 16 + ((grp & 1) << 3) + row) * QP
                                    + ((grp >> 1) << 3)) * 2);
    uint32_t soff[4], toff[4];
#pragma unroll
    for (int p = 0; p < 4; p++) {
        soff[p] = (uint32_t)((((2 * p + (grp >> 1)) * 8 + row) * QP
                             + ((grp & 1) << 3)) * 2);
        toff[p] = (uint32_t)(((((grp & 1) << 3) + row) * QP
                             + (2 * p + (grp >> 1)) * 8) * 2);
    }

#pragma unroll
    for (int p = 0; p < 4; p++) {
        int c = t + p * 256;
        int i = c >> 3, jc = c & 7;
        cp_async16(Ksu + (uint32_t)(i * QP + 8 * jc) * 2,
                   kb + (long)(k0 + i) * DD + 8 * jc);
    }
#pragma unroll
    for (int p = 0; p < 2; p++) {
        int c = t + p * 256;
        int i = c >> 3, jc = c & 7;
        cp_async16(Qau[0] + (uint32_t)(i * QP + 8 * jc) * 2,
                   qb + (long)i * DD + 8 * jc);
    }
    CP_COMMIT();

    float dka[8][4];
#pragma unroll
    for (int i = 0; i < 8; i++)
#pragma unroll
        for (int e = 0; e < 4; e++) dka[i][e] = 0.f;

    float pl = (t < 64) ? lse[(long)bh * NN + t] : 0.f;

    for (int c = 0; c < 16; c++) {
        const int buf = c & 1;
        if (c + 1 < 16) {
#pragma unroll
            for (int p = 0; p < 2; p++) {
                int cc = t + p * 256;
                int i = cc >> 3, jc = cc & 7;
                cp_async16(Qau[buf ^ 1] + (uint32_t)(i * QP + 8 * jc) * 2,
                           qb + (long)((c + 1) * 64 + i) * DD + 8 * jc);
            }
        }
        CP_COMMIT();
        CP_WAIT1();
        if (t < 64) sL[t] = pl;
        __syncthreads();
        if (c + 1 < 16 && t < 64) pl = lse[(long)bh * NN + (c + 1) * 64 + t];

        float s[8][4];
#pragma unroll
        for (int i = 0; i < 8; i++)
#pragma unroll
            for (int e = 0; e < 4; e++) s[i][e] = 0.f;
#pragma unroll
        for (int kc = 0; kc < 4; kc++) {
            uint32_t a[4], bf[8][2];
            ldsm_x4(a[0], a[1], a[2], a[3], Ksu + koff + kc * 32);
#pragma unroll
            for (int p = 0; p < 4; p++)
                ldsm_x4(bf[2 * p][0], bf[2 * p][1], bf[2 * p + 1][0], bf[2 * p + 1][1],
                        Qau[buf] + soff[p] + kc * 32);
#pragma unroll
            for (int nt = 0; nt < 8; nt++)
                mma_fp16(s[nt], a, bf[nt]);
        }

        uint32_t Pf[8][2];
#pragma unroll
        for (int nt = 0; nt < 8; nt++) {
            float ls0 = sL[nt * 8 + 2 * qc], ls1 = sL[nt * 8 + 2 * qc + 1];
            float p0 = __expf(s[nt][0] * BETA_ATT - ls0);
            float p1 = __expf(s[nt][1] * BETA_ATT - ls1);
            float p2 = __expf(s[nt][2] * BETA_ATT - ls0);
            float p3 = __expf(s[nt][3] * BETA_ATT - ls1);
            __half2 x = __floats2half2_rn(p0, p1); Pf[nt][0] = *(uint32_t*)&x;
            __half2 y = __floats2half2_rn(p2, p3); Pf[nt][1] = *(uint32_t*)&y;
        }
#pragma unroll
        for (int kc = 0; kc < 4; kc++) {
            uint32_t a[4] = { Pf[2 * kc][0], Pf[2 * kc][1],
                              Pf[2 * kc + 1][0], Pf[2 * kc + 1][1] };
            uint32_t bf[8][2];
#pragma unroll
            for (int p = 0; p < 4; p++)
                ldsm_x4_t(bf[2 * p][0], bf[2 * p][1], bf[2 * p + 1][0], bf[2 * p + 1][1],
                          Qau[buf] + toff[p] + (uint32_t)(kc * 16 * QP * 2));
#pragma unroll
            for (int nt = 0; nt < 8; nt++)
                mma_fp16(dka[nt], a, bf[nt]);
        }
        __syncthreads();
    }

    const int r0 = k0 + w * 16 + qr;
#pragma unroll
    for (int nt = 0; nt < 8; nt++) {
        int col = nt * 8 + 2 * qc;
        __half2 v0 = __floats2half2_rn(dka[nt][0], dka[nt][1]);
        __half2 v1 = __floats2half2_rn(dka[nt][2], dka[nt][3]);
        *(uint32_t*)(dkb + (long)r0 * DD + col) = *(uint32_t*)&v0;
        *(uint32_t*)(dkb + (long)(r0 + 8) * DD + col) = *(uint32_t*)&v1;
    }
}

// ===========================================================================
// LayerNorm (fp32 in, fp16 out); fused x-update variant
// ===========================================================================
template<int UPD>
__global__ __launch_bounds__(256)
void ln_kernel(float* __restrict__ x, const float* __restrict__ acc,
               const float* __restrict__ gamma, const float* __restrict__ beta,
               __half* __restrict__ g)
{
    const long base = (long)blockIdx.x * DD;
    const int t = threadIdx.x;
    float v[3];
    float s = 0.f, ss = 0.f;
#pragma unroll
    for (int i = 0; i < 3; i++) {
        long idx = base + t + i * 256;
        float xv = x[idx];
        if (UPD) { xv = fmaf(ALPHA, acc[idx], xv); x[idx] = xv; }
        v[i] = xv;
        s += xv;
        ss = fmaf(xv, xv, ss);
    }
#pragma unroll
    for (int o = 16; o > 0; o >>= 1) {
        s  += __shfl_xor_sync(0xffffffffu, s, o);
        ss += __shfl_xor_sync(0xffffffffu, ss, o);
    }
    __shared__ float rs[8], rss[8], bc[2];
    if ((t & 31) == 0) { rs[t >> 5] = s; rss[t >> 5] = ss; }
    __syncthreads();
    if (t == 0) {
        float a = 0.f, bsum = 0.f;
#pragma unroll
        for (int i = 0; i < 8; i++) { a += rs[i]; bsum += rss[i]; }
        float mean = a * (1.f / DD);
        float var  = bsum * (1.f / DD) - mean * mean;
        bc[0] = mean;
        bc[1] = rsqrtf(var + EPS_LN);
    }
    __syncthreads();
    const float mean = bc[0], rinv = bc[1];
#pragma unroll
    for (int i = 0; i < 3; i++) {
        int col = t + i * 256;
        g[base + col] = __float2half(gamma[col] * (v[i] - mean) * rinv + beta[col]);
    }
}

__global__ __launch_bounds__(256)
void update_kernel(float* __restrict__ x, const float* __restrict__ acc)
{
    long i = (long)blockIdx.x * 256 + threadIdx.x;
    x[i] = fmaf(ALPHA, acc[i], x[i]);
}

__global__ __launch_bounds__(256)
void prep_w(const float* __restrict__ W, __half* __restrict__ Wh,
            __half* __restrict__ WT, int R, int C)
{
    int i = blockIdx.x * 256 + threadIdx.x;
    if (i < R * C) {
        int r = i / C, c = i % C;
        __half h = __float2half(W[i]);
        Wh[i] = h;
        WT[(long)c * R + r] = h;
    }
}

// ===========================================================================
// Host
// ===========================================================================
static const int SMEMH = 3 * (128 + 256) * HP * 2;   // 165888 bytes

template<int OH>
static void hc(const __half* A, const __half* B, void* C, int M, int N, int K,
               long lda, long ldb, long ldc, float scale, int relu, int accum)
{
    cudaFuncSetAttribute(hgemm<OH>, cudaFuncAttributeMaxDynamicSharedMemorySize, SMEMH);
    dim3 grid(N / 256, M / 128, 1);
    hgemm<OH><<<grid, 256, SMEMH>>>(A, B, C, K, lda, ldb, ldc, scale, relu, accum);
}

extern "C" void kernel_launch(void* const* d_in, const int* in_sizes, int n_in,
                              void* d_out, int out_size)
{
    const float* x_in  = (const float*)d_in[0];
    const float* gamma = (const float*)d_in[1];
    const float* betaL = (const float*)d_in[2];
    const float* Wq    = (const float*)d_in[3];
    const float* Wk    = (const float*)d_in[4];
    const float* xi    = (const float*)d_in[5];

    float* xb = (float*)d_out;

    __half *g, *q, *k, *dq, *dk, *r, *wqh, *wkh, *xih, *wqT, *wkT, *xiT;
    float *acc, *lse;
    cudaGetSymbolAddress((void**)&g,   d_g);
    cudaGetSymbolAddress((void**)&q,   d_q);
    cudaGetSymbolAddress((void**)&k,   d_k);
    cudaGetSymbolAddress((void**)&dq,  d_dq);
    cudaGetSymbolAddress((void**)&dk,  d_dk);
    cudaGetSymbolAddress((void**)&r,   d_r);
    cudaGetSymbolAddress((void**)&acc, d_acc);
    cudaGetSymbolAddress((void**)&lse, d_lse);
    cudaGetSymbolAddress((void**)&wqh, d_wqh);
    cudaGetSymbolAddress((void**)&wkh, d_wkh);
    cudaGetSymbolAddress((void**)&xih, d_xih);
    cudaGetSymbolAddress((void**)&wqT, d_wqT);
    cudaGetSymbolAddress((void**)&wkT, d_wkT);
    cudaGetSymbolAddress((void**)&xiT, d_xiT);

    cudaMemcpyAsync(xb, x_in, (size_t)GSZ * sizeof(float), cudaMemcpyDeviceToDevice, 0);

    prep_w<<<(DD * DD + 255) / 256, 256>>>(Wq, wqh, wqT, DD, DD);
    prep_w<<<(DD * DD + 255) / 256, 256>>>(Wk, wkh, wkT, DD, DD);
    prep_w<<<(MM * DD + 255) / 256, 256>>>(xi, xih, xiT, MM, DD);

    ln_kernel<0><<<BN_TOK, 256>>>(xb, acc, gamma, betaL, g);

    for (int step = 0; step < STEPS; step++) {
        // q = g @ Wq^T ; k = g @ Wk^T  (fp16 out)
        hc<1>(g, wqh, q, BN_TOK, DD, DD, DD, DD, DD, 1.f, 0, 0);
        hc<1>(g, wkh, k, BN_TOK, DD, DD, DD, DD, DD, 1.f, 0, 0);

        // Flash attention gradients
        dq_flash<<<dim3(NN / 128, BB * HH), 256>>>(q, k, dq, lse);
        dk_flash<<<dim3(NN / 128, BB * HH), 256>>>(q, k, dk, lse);

        // acc = dq @ Wq ; acc += dk @ Wk
        hc<0>(dq, wqT, acc, BN_TOK, DD, DD, DD, DD, DD, 1.f, 0, 0);
        hc<0>(dk, wkT, acc, BN_TOK, DD, DD, DD, DD, DD, 1.f, 0, 1);

        // r = relu(g @ xi^T) ; acc += r @ xi
        hc<1>(g, xih, r, BN_TOK, MM, DD, DD, DD, MM, 1.f, 1, 0);
        hc<0>(r, xiT, acc, BN_TOK, DD, MM, MM, MM, DD, 1.f, 0, 1);

        // fused x-update + next-step layernorm (plain update on last step)
        if (step + 1 < STEPS)
            ln_kernel<1><<<BN_TOK, 256>>>(xb, acc, gamma, betaL, g);
        else
            update_kernel<<<GSZ / 256, 256>>>(xb, acc);
    }
}

// round 16
// speedup vs baseline: 1.3120x; 1.3120x over previous
#include <cuda_runtime.h>
#include <cuda_fp16.h>
#include <cstdint>
#include <math.h>

// Problem constants
#define BB 8
#define NN 1024
#define DD 768
#define HH 12
#define YY 64
#define MM 3072
#define STEPS 12
#define ALPHA 0.1f
#define EPS_LN 1e-5f
#define BETA_ATT 0.125f   // 1/sqrt(64)

#define BN_TOK (BB*NN)             // 8192
#define GSZ    (BB*NN*DD)          // 6291456
#define RSZ    (BB*NN*MM)          // 25165824
#define QLD    (2*DD)              // 1536: row stride of concatenated q|k

// Scratch (static __device__ arrays: sanctioned alloc-free workaround)
__device__ __half d_g[GSZ];
__device__ __half d_qk[2*GSZ];     // [8192][1536]: cols 0..767 = q, 768..1535 = k
__device__ __half d_dqk[2*GSZ];    // same layout for dq|dk
__device__ __half d_r[RSZ];
__device__ float  d_acc[GSZ];
__device__ float  d_lse[BB*HH*NN];
__device__ __half d_wqkh[2*DD*DD]; // [1536][768]: rows 0..767 = Wq, 768.. = Wk
__device__ __half d_wT2[2*DD*DD];  // [768][1536]: wT2[n][kk] = (kk<768?Wq:Wk)[kk%768][n]
__device__ __half d_xih[MM*DD];
__device__ __half d_xiT[DD*MM];

// ===========================================================================
// helpers
// ===========================================================================
__device__ __forceinline__ uint32_t smem_u32(const void* p) {
    uint32_t a;
    asm("{ .reg .u64 t; cvta.to.shared.u64 t, %1; cvt.u32.u64 %0, t; }"
        : "=r"(a) : "l"(p));
    return a;
}
__device__ __forceinline__ void mma_fp16(float* c, const uint32_t* a, const uint32_t* b) {
    asm volatile(
        "mma.sync.aligned.m16n8k16.row.col.f32.f16.f16.f32 "
        "{%0,%1,%2,%3}, {%4,%5,%6,%7}, {%8,%9}, {%0,%1,%2,%3};"
        : "+f"(c[0]), "+f"(c[1]), "+f"(c[2]), "+f"(c[3])
        : "r"(a[0]), "r"(a[1]), "r"(a[2]), "r"(a[3]), "r"(b[0]), "r"(b[1]));
}
__device__ __forceinline__ void ldsm_x4(uint32_t& r0, uint32_t& r1, uint32_t& r2,
                                        uint32_t& r3, uint32_t addr) {
    asm volatile("ldmatrix.sync.aligned.m8n8.x4.shared.b16 {%0,%1,%2,%3}, [%4];"
        : "=r"(r0), "=r"(r1), "=r"(r2), "=r"(r3) : "r"(addr));
}
__device__ __forceinline__ void ldsm_x4_t(uint32_t& r0, uint32_t& r1, uint32_t& r2,
                                          uint32_t& r3, uint32_t addr) {
    asm volatile("ldmatrix.sync.aligned.m8n8.x4.trans.shared.b16 {%0,%1,%2,%3}, [%4];"
        : "=r"(r0), "=r"(r1), "=r"(r2), "=r"(r3) : "r"(addr));
}
__device__ __forceinline__ void cp_async16(uint32_t dst, const void* src) {
    asm volatile("cp.async.cg.shared.global [%0], [%1], 16;" :: "r"(dst), "l"(src));
}
#define CP_COMMIT() asm volatile("cp.async.commit_group;" ::: "memory")
#define CP_WAIT1()  asm volatile("cp.async.wait_group 1;" ::: "memory")

#define HP 72      // halves per smem row (144B: 16B-aligned, LDSM conflict-free)
#define QP 72      // fp16 pitch, flash tiles

// ===========================================================================
// Generic fp16 GEMM (R12-validated): 128x128 tile, 8 warps (2x4) x 64x32,
// ldmatrix fragments, cp.async double-buffer K=64, 2 CTAs/SM.
//   C[m,n] = (accum?C:0) + scale * sum_k A[m][k]*B[n][k]   (+relu)
//   OH=1: C is __half;  OH=0: C is float.
// ===========================================================================
__device__ __forceinline__ void stageH(uint32_t dstu, const __half* __restrict__ src,
                                       int r0, int k0, long ld, int t)
{
#pragma unroll
    for (int p = 0; p < 4; p++) {
        int c = t + p * 256;
        int i = c >> 3, jc = c & 7;
        cp_async16(dstu + (uint32_t)(i * HP + 8 * jc) * 2,
                   src + (long)(r0 + i) * ld + k0 + 8 * jc);
    }
}

template<int OH>
__global__ __launch_bounds__(256, 2)
void hgemm(const __half* __restrict__ A, const __half* __restrict__ B,
           void* __restrict__ Cv, int Kdim, long lda, long ldb, long ldc,
           float scale, int relu, int accum)
{
    extern __shared__ __half sh[];
    constexpr int AW = 128 * HP;
    const uint32_t smu = smem_u32(sh);
    const uint32_t Au[2] = { smu, smu + AW * 2 };
    const uint32_t Bu[2] = { smu + 2 * AW * 2, smu + 3 * AW * 2 };

    const int t = threadIdx.x, lane = t & 31, wid = t >> 5;
    const int wm = wid & 1, wn = wid >> 1;
    const int qr = lane >> 2, qc = lane & 3;
    const int grp = lane >> 3, row = lane & 7;
    const int m0 = blockIdx.y * 128;
    const int n0 = blockIdx.x * 128;

    uint32_t aoff[4], boff[2];
#pragma unroll
    for (int mt = 0; mt < 4; mt++)
        aoff[mt] = (uint32_t)(((wm * 64 + mt * 16 + ((grp & 1) << 3) + row) * HP
                             + ((grp >> 1) << 3)) * 2);
#pragma unroll
    for (int p = 0; p < 2; p++)
        boff[p] = (uint32_t)(((wn * 32 + (2 * p + (grp >> 1)) * 8 + row) * HP
                             + ((grp & 1) << 3)) * 2);

    float acc[4][4][4];
#pragma unroll
    for (int i = 0; i < 4; i++)
#pragma unroll
        for (int j = 0; j < 4; j++)
#pragma unroll
            for (int e = 0; e < 4; e++) acc[i][j][e] = 0.f;

    const int CH = Kdim >> 6;
    stageH(Au[0], A, m0, 0, lda, t);
    stageH(Bu[0], B, n0, 0, ldb, t);
    CP_COMMIT();

    for (int c = 0; c < CH; c++) {
        const int buf = c & 1;
        if (c + 1 < CH) {
            stageH(Au[buf ^ 1], A, m0, (c + 1) * 64, lda, t);
            stageH(Bu[buf ^ 1], B, n0, (c + 1) * 64, ldb, t);
        }
        CP_COMMIT();
        CP_WAIT1();
        __syncthreads();

#pragma unroll
        for (int ks = 0; ks < 4; ks++) {
            uint32_t af[4][4], bf[4][2];
#pragma unroll
            for (int mt = 0; mt < 4; mt++)
                ldsm_x4(af[mt][0], af[mt][1], af[mt][2], af[mt][3],
                        Au[buf] + aoff[mt] + ks * 32);
#pragma unroll
            for (int p = 0; p < 2; p++)
                ldsm_x4(bf[2 * p][0], bf[2 * p][1], bf[2 * p + 1][0], bf[2 * p + 1][1],
                        Bu[buf] + boff[p] + ks * 32);
#pragma unroll
            for (int mt = 0; mt < 4; mt++)
#pragma unroll
                for (int nt = 0; nt < 4; nt++)
                    mma_fp16(acc[mt][nt], af[mt], bf[nt]);
        }
        __syncthreads();
    }

#pragma unroll
    for (int mt = 0; mt < 4; mt++) {
        int rw = m0 + wm * 64 + mt * 16 + qr;
#pragma unroll
        for (int nt = 0; nt < 4; nt++) {
            int col = n0 + wn * 32 + nt * 8 + (qc << 1);
#pragma unroll
            for (int h = 0; h < 2; h++) {
                long idx = (long)(rw + 8 * h) * ldc + col;
                float v0 = acc[mt][nt][2 * h + 0] * scale;
                float v1 = acc[mt][nt][2 * h + 1] * scale;
                if (relu) { v0 = fmaxf(v0, 0.f); v1 = fmaxf(v1, 0.f); }
                if (OH) {
                    __half2 w = __floats2half2_rn(v0, v1);
                    *(uint32_t*)&((__half*)Cv)[idx] = *(uint32_t*)&w;
                } else {
                    float* C = (float*)Cv;
                    if (accum) {
                        float2 o = *(const float2*)&C[idx];
                        v0 += o.x; v1 += o.y;
                    }
                    float2 w; w.x = v0; w.y = v1;
                    *(float2*)&C[idx] = w;
                }
            }
        }
    }
}

// ===========================================================================
// Flash attention gradients (row stride QLD=1536 for the concatenated q|k).
// ===========================================================================
__global__ __launch_bounds__(256, 2)
void dq_flash(const __half* __restrict__ qg, const __half* __restrict__ kg,
              __half* __restrict__ dqg, float* __restrict__ lse)
{
    __shared__ __half Qs[128 * QP];
    __shared__ __half Ka[2][64 * QP];

    const int t = threadIdx.x, lane = t & 31, w = t >> 5;
    const int qr = lane >> 2, qc = lane & 3;
    const int grp = lane >> 3, row = lane & 7;
    const int q0 = blockIdx.x * 128;
    const int bh = blockIdx.y;
    const int b = bh / HH, h = bh % HH;
    const __half* qb = qg + (long)b * NN * QLD + h * YY;
    const __half* kb = kg + (long)b * NN * QLD + h * YY;
    __half* dqb = dqg + (long)b * NN * QLD + h * YY;

    const uint32_t Qsu = smem_u32(Qs);
    const uint32_t Kau[2] = { smem_u32(Ka[0]), smem_u32(Ka[1]) };

    const uint32_t qoff = (uint32_t)(((w * 16 + ((grp & 1) << 3) + row) * QP
                                    + ((grp >> 1) << 3)) * 2);
    uint32_t soff[4], toff[4];
#pragma unroll
    for (int p = 0; p < 4; p++) {
        soff[p] = (uint32_t)((((2 * p + (grp >> 1)) * 8 + row) * QP
                             + ((grp & 1) << 3)) * 2);
        toff[p] = (uint32_t)(((((grp & 1) << 3) + row) * QP
                             + (2 * p + (grp >> 1)) * 8) * 2);
    }

#pragma unroll
    for (int p = 0; p < 4; p++) {
        int c = t + p * 256;
        int i = c >> 3, jc = c & 7;
        cp_async16(Qsu + (uint32_t)(i * QP + 8 * jc) * 2,
                   qb + (long)(q0 + i) * QLD + 8 * jc);
    }
#pragma unroll
    for (int p = 0; p < 2; p++) {
        int c = t + p * 256;
        int i = c >> 3, jc = c & 7;
        cp_async16(Kau[0] + (uint32_t)(i * QP + 8 * jc) * 2,
                   kb + (long)i * QLD + 8 * jc);
    }
    CP_COMMIT();

    float m0 = -1e30f, m1 = -1e30f, l0 = 0.f, l1 = 0.f;
    float dqa[8][4];
#pragma unroll
    for (int i = 0; i < 8; i++)
#pragma unroll
        for (int e = 0; e < 4; e++) dqa[i][e] = 0.f;

    for (int c = 0; c < 16; c++) {
        const int buf = c & 1;
        if (c + 1 < 16) {
#pragma unroll
            for (int p = 0; p < 2; p++) {
                int cc = t + p * 256;
                int i = cc >> 3, jc = cc & 7;
                cp_async16(Kau[buf ^ 1] + (uint32_t)(i * QP + 8 * jc) * 2,
                           kb + (long)((c + 1) * 64 + i) * QLD + 8 * jc);
            }
        }
        CP_COMMIT();
        CP_WAIT1();
        __syncthreads();

        float s[8][4];
#pragma unroll
        for (int i = 0; i < 8; i++)
#pragma unroll
            for (int e = 0; e < 4; e++) s[i][e] = 0.f;
#pragma unroll
        for (int kc = 0; kc < 4; kc++) {
            uint32_t a[4], bf[8][2];
            ldsm_x4(a[0], a[1], a[2], a[3], Qsu + qoff + kc * 32);
#pragma unroll
            for (int p = 0; p < 4; p++)
                ldsm_x4(bf[2 * p][0], bf[2 * p][1], bf[2 * p + 1][0], bf[2 * p + 1][1],
                        Kau[buf] + soff[p] + kc * 32);
#pragma unroll
            for (int nt = 0; nt < 8; nt++)
                mma_fp16(s[nt], a, bf[nt]);
        }
#pragma unroll
        for (int nt = 0; nt < 8; nt++)
#pragma unroll
            for (int e = 0; e < 4; e++) s[nt][e] *= BETA_ATT;

        float bm0 = -1e30f, bm1 = -1e30f;
#pragma unroll
        for (int nt = 0; nt < 8; nt++) {
            bm0 = fmaxf(bm0, fmaxf(s[nt][0], s[nt][1]));
            bm1 = fmaxf(bm1, fmaxf(s[nt][2], s[nt][3]));
        }
        bm0 = fmaxf(bm0, __shfl_xor_sync(0xffffffffu, bm0, 1));
        bm0 = fmaxf(bm0, __shfl_xor_sync(0xffffffffu, bm0, 2));
        bm1 = fmaxf(bm1, __shfl_xor_sync(0xffffffffu, bm1, 1));
        bm1 = fmaxf(bm1, __shfl_xor_sync(0xffffffffu, bm1, 2));
        float mn0 = fmaxf(m0, bm0), mn1 = fmaxf(m1, bm1);
        float rs0 = __expf(m0 - mn0), rs1 = __expf(m1 - mn1);
        m0 = mn0; m1 = mn1;

        uint32_t Pf[8][2];
        float lp0 = 0.f, lp1 = 0.f;
#pragma unroll
        for (int nt = 0; nt < 8; nt++) {
            float p0 = __expf(s[nt][0] - m0), p1 = __expf(s[nt][1] - m0);
            float p2 = __expf(s[nt][2] - m1), p3 = __expf(s[nt][3] - m1);
            lp0 += p0 + p1; lp1 += p2 + p3;
            __half2 x = __floats2half2_rn(p0, p1); Pf[nt][0] = *(uint32_t*)&x;
            __half2 y = __floats2half2_rn(p2, p3); Pf[nt][1] = *(uint32_t*)&y;
        }
        l0 = l0 * rs0 + lp0; l1 = l1 * rs1 + lp1;
#pragma unroll
        for (int nt = 0; nt < 8; nt++) {
            dqa[nt][0] *= rs0; dqa[nt][1] *= rs0;
            dqa[nt][2] *= rs1; dqa[nt][3] *= rs1;
        }

#pragma unroll
        for (int kc = 0; kc < 4; kc++) {
            uint32_t a[4] = { Pf[2 * kc][0], Pf[2 * kc][1],
                              Pf[2 * kc + 1][0], Pf[2 * kc + 1][1] };
            uint32_t bf[8][2];
#pragma unroll
            for (int p = 0; p < 4; p++)
                ldsm_x4_t(bf[2 * p][0], bf[2 * p][1], bf[2 * p + 1][0], bf[2 * p + 1][1],
                          Kau[buf] + toff[p] + (uint32_t)(kc * 16 * QP * 2));
#pragma unroll
            for (int nt = 0; nt < 8; nt++)
                mma_fp16(dqa[nt], a, bf[nt]);
        }
        __syncthreads();
    }

    l0 += __shfl_xor_sync(0xffffffffu, l0, 1);
    l0 += __shfl_xor_sync(0xffffffffu, l0, 2);
    l1 += __shfl_xor_sync(0xffffffffu, l1, 1);
    l1 += __shfl_xor_sync(0xffffffffu, l1, 2);
    const float li0 = 1.f / l0, li1 = 1.f / l1;

    const int r0 = q0 + w * 16 + qr;
#pragma unroll
    for (int nt = 0; nt < 8; nt++) {
        int col = nt * 8 + 2 * qc;
        __half2 v0 = __floats2half2_rn(dqa[nt][0] * li0, dqa[nt][1] * li0);
        __half2 v1 = __floats2half2_rn(dqa[nt][2] * li1, dqa[nt][3] * li1);
        *(uint32_t*)(dqb + (long)r0 * QLD + col) = *(uint32_t*)&v0;
        *(uint32_t*)(dqb + (long)(r0 + 8) * QLD + col) = *(uint32_t*)&v1;
    }
    if (qc == 0) {
        lse[(long)bh * NN + r0]     = m0 + logf(l0);
        lse[(long)bh * NN + r0 + 8] = m1 + logf(l1);
    }
}

__global__ __launch_bounds__(256, 2)
void dk_flash(const __half* __restrict__ qg, const __half* __restrict__ kg,
              __half* __restrict__ dkg, const float* __restrict__ lse)
{
    __shared__ __half Ks[128 * QP];
    __shared__ __half Qa[2][64 * QP];
    __shared__ float sL[64];

    const int t = threadIdx.x, lane = t & 31, w = t >> 5;
    const int qr = lane >> 2, qc = lane & 3;
    const int grp = lane >> 3, row = lane & 7;
    const int k0 = blockIdx.x * 128;
    const int bh = blockIdx.y;
    const int b = bh / HH, h = bh % HH;
    const __half* qb = qg + (long)b * NN * QLD + h * YY;
    const __half* kb = kg + (long)b * NN * QLD + h * YY;
    __half* dkb = dkg + (long)b * NN * QLD + h * YY;

    const uint32_t Ksu = smem_u32(Ks);
    const uint32_t Qau[2] = { smem_u32(Qa[0]), smem_u32(Qa[1]) };

    const uint32_t koff = (uint32_t)(((w * 16 + ((grp & 1) << 3) + row) * QP
                                    + ((grp >> 1) << 3)) * 2);
    uint32_t soff[4], toff[4];
#pragma unroll
    for (int p = 0; p < 4; p++) {
        soff[p] = (uint32_t)((((2 * p + (grp >> 1)) * 8 + row) * QP
                             + ((grp & 1) << 3)) * 2);
        toff[p] = (uint32_t)(((((grp & 1) << 3) + row) * QP
                             + (2 * p + (grp >> 1)) * 8) * 2);
    }

#pragma unroll
    for (int p = 0; p < 4; p++) {
        int c = t + p * 256;
        int i = c >> 3, jc = c & 7;
        cp_async16(Ksu + (uint32_t)(i * QP + 8 * jc) * 2,
                   kb + (long)(k0 + i) * QLD + 8 * jc);
    }
#pragma unroll
    for (int p = 0; p < 2; p++) {
        int c = t + p * 256;
        int i = c >> 3, jc = c & 7;
        cp_async16(Qau[0] + (uint32_t)(i * QP + 8 * jc) * 2,
                   qb + (long)i * QLD + 8 * jc);
    }
    CP_COMMIT();

    float dka[8][4];
#pragma unroll
    for (int i = 0; i < 8; i++)
#pragma unroll
        for (int e = 0; e < 4; e++) dka[i][e] = 0.f;

    float pl = (t < 64) ? lse[(long)bh * NN + t] : 0.f;

    for (int c = 0; c < 16; c++) {
        const int buf = c & 1;
        if (c + 1 < 16) {
#pragma unroll
            for (int p = 0; p < 2; p++) {
                int cc = t + p * 256;
                int i = cc >> 3, jc = cc & 7;
                cp_async16(Qau[buf ^ 1] + (uint32_t)(i * QP + 8 * jc) * 2,
                           qb + (long)((c + 1) * 64 + i) * QLD + 8 * jc);
            }
        }
        CP_COMMIT();
        CP_WAIT1();
        if (t < 64) sL[t] = pl;
        __syncthreads();
        if (c + 1 < 16 && t < 64) pl = lse[(long)bh * NN + (c + 1) * 64 + t];

        float s[8][4];
#pragma unroll
        for (int i = 0; i < 8; i++)
#pragma unroll
            for (int e = 0; e < 4; e++) s[i][e] = 0.f;
#pragma unroll
        for (int kc = 0; kc < 4; kc++) {
            uint32_t a[4], bf[8][2];
            ldsm_x4(a[0], a[1], a[2], a[3], Ksu + koff + kc * 32);
#pragma unroll
            for (int p = 0; p < 4; p++)
                ldsm_x4(bf[2 * p][0], bf[2 * p][1], bf[2 * p + 1][0], bf[2 * p + 1][1],
                        Qau[buf] + soff[p] + kc * 32);
#pragma unroll
            for (int nt = 0; nt < 8; nt++)
                mma_fp16(s[nt], a, bf[nt]);
        }

        uint32_t Pf[8][2];
#pragma unroll
        for (int nt = 0; nt < 8; nt++) {
            float ls0 = sL[nt * 8 + 2 * qc], ls1 = sL[nt * 8 + 2 * qc + 1];
            float p0 = __expf(s[nt][0] * BETA_ATT - ls0);
            float p1 = __expf(s[nt][1] * BETA_ATT - ls1);
            float p2 = __expf(s[nt][2] * BETA_ATT - ls0);
            float p3 = __expf(s[nt][3] * BETA_ATT - ls1);
            __half2 x = __floats2half2_rn(p0, p1); Pf[nt][0] = *(uint32_t*)&x;
            __half2 y = __floats2half2_rn(p2, p3); Pf[nt][1] = *(uint32_t*)&y;
        }
#pragma unroll
        for (int kc = 0; kc < 4; kc++) {
            uint32_t a[4] = { Pf[2 * kc][0], Pf[2 * kc][1],
                              Pf[2 * kc + 1][0], Pf[2 * kc + 1][1] };
            uint32_t bf[8][2];
#pragma unroll
            for (int p = 0; p < 4; p++)
                ldsm_x4_t(bf[2 * p][0], bf[2 * p][1], bf[2 * p + 1][0], bf[2 * p + 1][1],
                          Qau[buf] + toff[p] + (uint32_t)(kc * 16 * QP * 2));
#pragma unroll
            for (int nt = 0; nt < 8; nt++)
                mma_fp16(dka[nt], a, bf[nt]);
        }
        __syncthreads();
    }

    const int r0 = k0 + w * 16 + qr;
#pragma unroll
    for (int nt = 0; nt < 8; nt++) {
        int col = nt * 8 + 2 * qc;
        __half2 v0 = __floats2half2_rn(dka[nt][0], dka[nt][1]);
        __half2 v1 = __floats2half2_rn(dka[nt][2], dka[nt][3]);
        *(uint32_t*)(dkb + (long)r0 * QLD + col) = *(uint32_t*)&v0;
        *(uint32_t*)(dkb + (long)(r0 + 8) * QLD + col) = *(uint32_t*)&v1;
    }
}

// ===========================================================================
// LayerNorm (fp32 in, fp16 out); fused x-update variant
// ===========================================================================
template<int UPD>
__global__ __launch_bounds__(256)
void ln_kernel(float* __restrict__ x, const float* __restrict__ acc,
               const float* __restrict__ gamma, const float* __restrict__ beta,
               __half* __restrict__ g)
{
    const long base = (long)blockIdx.x * DD;
    const int t = threadIdx.x;
    float v[3];
    float s = 0.f, ss = 0.f;
#pragma unroll
    for (int i = 0; i < 3; i++) {
        long idx = base + t + i * 256;
        float xv = x[idx];
        if (UPD) { xv = fmaf(ALPHA, acc[idx], xv); x[idx] = xv; }
        v[i] = xv;
        s += xv;
        ss = fmaf(xv, xv, ss);
    }
#pragma unroll
    for (int o = 16; o > 0; o >>= 1) {
        s  += __shfl_xor_sync(0xffffffffu, s, o);
        ss += __shfl_xor_sync(0xffffffffu, ss, o);
    }
    __shared__ float rs[8], rss[8], bc[2];
    if ((t & 31) == 0) { rs[t >> 5] = s; rss[t >> 5] = ss; }
    __syncthreads();
    if (t == 0) {
        float a = 0.f, bsum = 0.f;
#pragma unroll
        for (int i = 0; i < 8; i++) { a += rs[i]; bsum += rss[i]; }
        float mean = a * (1.f / DD);
        float var  = bsum * (1.f / DD) - mean * mean;
        bc[0] = mean;
        bc[1] = rsqrtf(var + EPS_LN);
    }
    __syncthreads();
    const float mean = bc[0], rinv = bc[1];
#pragma unroll
    for (int i = 0; i < 3; i++) {
        int col = t + i * 256;
        g[base + col] = __float2half(gamma[col] * (v[i] - mean) * rinv + beta[col]);
    }
}

__global__ __launch_bounds__(256)
void update_kernel(float* __restrict__ x, const float* __restrict__ acc)
{
    long i = (long)blockIdx.x * 256 + threadIdx.x;
    x[i] = fmaf(ALPHA, acc[i], x[i]);
}

// Build concatenated projection weights: wqkh [1536][768], wT2 [768][1536]
__global__ __launch_bounds__(256)
void prep_qk(const float* __restrict__ Wq, const float* __restrict__ Wk,
             __half* __restrict__ wqkh, __half* __restrict__ wT2)
{
    int i = blockIdx.x * 256 + threadIdx.x;
    if (i < DD * DD) {
        int r = i / DD, c = i % DD;
        __half hq = __float2half(Wq[i]);
        __half hk = __float2half(Wk[i]);
        wqkh[i] = hq;
        wqkh[(long)(DD + r) * DD + c] = hk;
        wT2[(long)c * QLD + r] = hq;
        wT2[(long)c * QLD + DD + r] = hk;
    }
}

__global__ __launch_bounds__(256)
void prep_xi(const float* __restrict__ X, __half* __restrict__ Xh,
             __half* __restrict__ XT)
{
    int i = blockIdx.x * 256 + threadIdx.x;
    if (i < MM * DD) {
        int r = i / DD, c = i % DD;
        __half h = __float2half(X[i]);
        Xh[i] = h;
        XT[(long)c * MM + r] = h;
    }
}

// ===========================================================================
// Host
// ===========================================================================
static const int SMEMH = 4 * 128 * HP * 2;   // 73728 bytes

template<int OH>
static void hc(const __half* A, const __half* B, void* C, int M, int N, int K,
               long lda, long ldb, long ldc, float scale, int relu, int accum)
{
    cudaFuncSetAttribute(hgemm<OH>, cudaFuncAttributeMaxDynamicSharedMemorySize, SMEMH);
    dim3 grid(N / 128, M / 128, 1);
    hgemm<OH><<<grid, 256, SMEMH>>>(A, B, C, K, lda, ldb, ldc, scale, relu, accum);
}

extern "C" void kernel_launch(void* const* d_in, const int* in_sizes, int n_in,
                              void* d_out, int out_size)
{
    const float* x_in  = (const float*)d_in[0];
    const float* gamma = (const float*)d_in[1];
    const float* betaL = (const float*)d_in[2];
    const float* Wq    = (const float*)d_in[3];
    const float* Wk    = (const float*)d_in[4];
    const float* xi    = (const float*)d_in[5];

    float* xb = (float*)d_out;

    __half *g, *qk, *dqk, *r, *wqkh, *wT2, *xih, *xiT;
    float *acc, *lse;
    cudaGetSymbolAddress((void**)&g,    d_g);
    cudaGetSymbolAddress((void**)&qk,   d_qk);
    cudaGetSymbolAddress((void**)&dqk,  d_dqk);
    cudaGetSymbolAddress((void**)&r,    d_r);
    cudaGetSymbolAddress((void**)&acc,  d_acc);
    cudaGetSymbolAddress((void**)&lse,  d_lse);
    cudaGetSymbolAddress((void**)&wqkh, d_wqkh);
    cudaGetSymbolAddress((void**)&wT2,  d_wT2);
    cudaGetSymbolAddress((void**)&xih,  d_xih);
    cudaGetSymbolAddress((void**)&xiT,  d_xiT);

    cudaMemcpyAsync(xb, x_in, (size_t)GSZ * sizeof(float), cudaMemcpyDeviceToDevice, 0);

    prep_qk<<<(DD * DD + 255) / 256, 256>>>(Wq, Wk, wqkh, wT2);
    prep_xi<<<(MM * DD + 255) / 256, 256>>>(xi, xih, xiT);

    ln_kernel<0><<<BN_TOK, 256>>>(xb, acc, gamma, betaL, g);

    for (int step = 0; step < STEPS; step++) {
        // qk = g @ [Wq;Wk]^T   one GEMM, N=1536
        hc<1>(g, wqkh, qk, BN_TOK, QLD, DD, DD, DD, QLD, 1.f, 0, 0);

        // Flash attention gradients (q = qk col 0, k = qk col 768)
        dq_flash<<<dim3(NN / 128, BB * HH), 256>>>(qk, qk + DD, dqk, lse);
        dk_flash<<<dim3(NN / 128, BB * HH), 256>>>(qk, qk + DD, dqk + DD, lse);

        // acc = [dq|dk] @ [Wq;Wk]   one GEMM, K=1536 (no accumulate pass)
        hc<0>(dqk, wT2, acc, BN_TOK, DD, QLD, QLD, QLD, DD, 1.f, 0, 0);

        // r = relu(g @ xi^T) ; acc += r @ xi
        hc<1>(g, xih, r, BN_TOK, MM, DD, DD, DD, MM, 1.f, 1, 0);
        hc<0>(r, xiT, acc, BN_TOK, DD, MM, MM, MM, DD, 1.f, 0, 1);

        // fused x-update + next-step layernorm (plain update on last step)
        if (step + 1 < STEPS)
            ln_kernel<1><<<BN_TOK, 256>>>(xb, acc, gamma, betaL, g);
        else
            update_kernel<<<GSZ / 256, 256>>>(xb, acc);
    }
}

// round 17
// speedup vs baseline: 1.3526x; 1.0309x over previous
#include <cuda_runtime.h>
#include <cuda_fp16.h>
#include <cstdint>
#include <math.h>

// Problem constants
#define BB 8
#define NN 1024
#define DD 768
#define HH 12
#define YY 64
#define MM 3072
#define STEPS 12
#define ALPHA 0.1f
#define EPS_LN 1e-5f
#define BETA_ATT 0.125f   // 1/sqrt(64)

#define BN_TOK (BB*NN)             // 8192
#define GSZ    (BB*NN*DD)          // 6291456
#define RSZ    (BB*NN*MM)          // 25165824
#define QLD    (2*DD)              // 1536: row stride of concatenated q|k

// Scratch (static __device__ arrays: sanctioned alloc-free workaround)
__device__ __half d_g[GSZ];
__device__ __half d_qk[2*GSZ];     // [8192][1536]: cols 0..767 = q, 768..1535 = k
__device__ __half d_dqk[2*GSZ];    // same layout for dq|dk
__device__ __half d_r[RSZ];
__device__ float  d_acc[GSZ];
__device__ float  d_lse[BB*HH*NN];
__device__ __half d_wqkh[2*DD*DD]; // [1536][768]: rows 0..767 = Wq, 768.. = Wk
__device__ __half d_wT2[2*DD*DD];  // [768][1536]
__device__ __half d_xih[MM*DD];
__device__ __half d_xiT[DD*MM];

// ===========================================================================
// helpers
// ===========================================================================
__device__ __forceinline__ uint32_t smem_u32(const void* p) {
    uint32_t a;
    asm("{ .reg .u64 t; cvta.to.shared.u64 t, %1; cvt.u32.u64 %0, t; }"
        : "=r"(a) : "l"(p));
    return a;
}
__device__ __forceinline__ void mma_fp16(float* c, const uint32_t* a, const uint32_t* b) {
    asm volatile(
        "mma.sync.aligned.m16n8k16.row.col.f32.f16.f16.f32 "
        "{%0,%1,%2,%3}, {%4,%5,%6,%7}, {%8,%9}, {%0,%1,%2,%3};"
        : "+f"(c[0]), "+f"(c[1]), "+f"(c[2]), "+f"(c[3])
        : "r"(a[0]), "r"(a[1]), "r"(a[2]), "r"(a[3]), "r"(b[0]), "r"(b[1]));
}
__device__ __forceinline__ void ldsm_x4(uint32_t& r0, uint32_t& r1, uint32_t& r2,
                                        uint32_t& r3, uint32_t addr) {
    asm volatile("ldmatrix.sync.aligned.m8n8.x4.shared.b16 {%0,%1,%2,%3}, [%4];"
        : "=r"(r0), "=r"(r1), "=r"(r2), "=r"(r3) : "r"(addr));
}
__device__ __forceinline__ void ldsm_x4_t(uint32_t& r0, uint32_t& r1, uint32_t& r2,
                                          uint32_t& r3, uint32_t addr) {
    asm volatile("ldmatrix.sync.aligned.m8n8.x4.trans.shared.b16 {%0,%1,%2,%3}, [%4];"
        : "=r"(r0), "=r"(r1), "=r"(r2), "=r"(r3) : "r"(addr));
}
__device__ __forceinline__ void cp_async16(uint32_t dst, const void* src) {
    asm volatile("cp.async.cg.shared.global [%0], [%1], 16;" :: "r"(dst), "l"(src));
}
#define CP_COMMIT() asm volatile("cp.async.commit_group;" ::: "memory")
#define CP_WAIT1()  asm volatile("cp.async.wait_group 1;" ::: "memory")

#define HP 72      // halves per smem row (144B: 16B-aligned, LDSM conflict-free)
#define QP 72      // fp16 pitch, flash tiles

// ===========================================================================
// Generic fp16 GEMM: 128x128 tile, 8 warps (2x4) x 64x32, ldmatrix frags,
// cp.async 3-STAGE pipeline (CUTLASS order, ONE barrier/chunk), 2 CTAs/SM.
//   C[m,n] = (accum?C:0) + scale * sum_k A[m][k]*B[n][k]   (+relu)
//   OH=1: C is __half;  OH=0: C is float.
// ===========================================================================
__device__ __forceinline__ void stageH(uint32_t dstu, const __half* __restrict__ src,
                                       int r0, int k0, long ld, int t)
{
#pragma unroll
    for (int p = 0; p < 4; p++) {
        int c = t + p * 256;
        int i = c >> 3, jc = c & 7;
        cp_async16(dstu + (uint32_t)(i * HP + 8 * jc) * 2,
                   src + (long)(r0 + i) * ld + k0 + 8 * jc);
    }
}

template<int OH>
__global__ __launch_bounds__(256, 2)
void hgemm(const __half* __restrict__ A, const __half* __restrict__ B,
           void* __restrict__ Cv, int Kdim, long lda, long ldb, long ldc,
           float scale, int relu, int accum)
{
    extern __shared__ __half sh[];
    constexpr int AW = 128 * HP;           // halves per A tile
    constexpr int SW = 2 * AW;             // halves per stage (A+B)
    const uint32_t smu = smem_u32(sh);
    uint32_t Au[3], Bu[3];
#pragma unroll
    for (int s = 0; s < 3; s++) {
        Au[s] = smu + (uint32_t)(s * SW) * 2;
        Bu[s] = Au[s] + AW * 2;
    }

    const int t = threadIdx.x, lane = t & 31, wid = t >> 5;
    const int wm = wid & 1, wn = wid >> 1;
    const int qr = lane >> 2, qc = lane & 3;
    const int grp = lane >> 3, row = lane & 7;
    const int m0 = blockIdx.y * 128;
    const int n0 = blockIdx.x * 128;

    uint32_t aoff[4], boff[2];
#pragma unroll
    for (int mt = 0; mt < 4; mt++)
        aoff[mt] = (uint32_t)(((wm * 64 + mt * 16 + ((grp & 1) << 3) + row) * HP
                             + ((grp >> 1) << 3)) * 2);
#pragma unroll
    for (int p = 0; p < 2; p++)
        boff[p] = (uint32_t)(((wn * 32 + (2 * p + (grp >> 1)) * 8 + row) * HP
                             + ((grp & 1) << 3)) * 2);

    float acc[4][4][4];
#pragma unroll
    for (int i = 0; i < 4; i++)
#pragma unroll
        for (int j = 0; j < 4; j++)
#pragma unroll
            for (int e = 0; e < 4; e++) acc[i][j][e] = 0.f;

    const int CH = Kdim >> 6;

    // prologue: stage chunks 0 and 1 (two committed groups)
    stageH(Au[0], A, m0, 0, lda, t);
    stageH(Bu[0], B, n0, 0, ldb, t);
    CP_COMMIT();
    if (CH > 1) {
        stageH(Au[1], A, m0, 64, lda, t);
        stageH(Bu[1], B, n0, 64, ldb, t);
    }
    CP_COMMIT();

    int buf = 0;
    for (int c = 0; c < CH; c++) {
        CP_WAIT1();              // chunk c resident (<=1 group pending)
        __syncthreads();         // cross-thread visibility + guards buffer reuse
        // stage chunk c+2 into buffer (c+2)%3 — overlapped with compute below
        if (c + 2 < CH) {
            int nb = buf + 2; if (nb >= 3) nb -= 3;
            stageH(Au[nb], A, m0, (c + 2) * 64, lda, t);
            stageH(Bu[nb], B, n0, (c + 2) * 64, ldb, t);
        }
        CP_COMMIT();

#pragma unroll
        for (int ks = 0; ks < 4; ks++) {
            uint32_t af[4][4], bf[4][2];
#pragma unroll
            for (int mt = 0; mt < 4; mt++)
                ldsm_x4(af[mt][0], af[mt][1], af[mt][2], af[mt][3],
                        Au[buf] + aoff[mt] + ks * 32);
#pragma unroll
            for (int p = 0; p < 2; p++)
                ldsm_x4(bf[2 * p][0], bf[2 * p][1], bf[2 * p + 1][0], bf[2 * p + 1][1],
                        Bu[buf] + boff[p] + ks * 32);
#pragma unroll
            for (int mt = 0; mt < 4; mt++)
#pragma unroll
                for (int nt = 0; nt < 4; nt++)
                    mma_fp16(acc[mt][nt], af[mt], bf[nt]);
        }
        if (++buf == 3) buf = 0;
    }

#pragma unroll
    for (int mt = 0; mt < 4; mt++) {
        int rw = m0 + wm * 64 + mt * 16 + qr;
#pragma unroll
        for (int nt = 0; nt < 4; nt++) {
            int col = n0 + wn * 32 + nt * 8 + (qc << 1);
#pragma unroll
            for (int h = 0; h < 2; h++) {
                long idx = (long)(rw + 8 * h) * ldc + col;
                float v0 = acc[mt][nt][2 * h + 0] * scale;
                float v1 = acc[mt][nt][2 * h + 1] * scale;
                if (relu) { v0 = fmaxf(v0, 0.f); v1 = fmaxf(v1, 0.f); }
                if (OH) {
                    __half2 w = __floats2half2_rn(v0, v1);
                    *(uint32_t*)&((__half*)Cv)[idx] = *(uint32_t*)&w;
                } else {
                    float* C = (float*)Cv;
                    if (accum) {
                        float2 o = *(const float2*)&C[idx];
                        v0 += o.x; v1 += o.y;
                    }
                    float2 w; w.x = v0; w.y = v1;
                    *(float2*)&C[idx] = w;
                }
            }
        }
    }
}

// ===========================================================================
// Flash attention gradients (row stride QLD=1536 for the concatenated q|k).
// ===========================================================================
__global__ __launch_bounds__(256, 2)
void dq_flash(const __half* __restrict__ qg, const __half* __restrict__ kg,
              __half* __restrict__ dqg, float* __restrict__ lse)
{
    __shared__ __half Qs[128 * QP];
    __shared__ __half Ka[2][64 * QP];

    const int t = threadIdx.x, lane = t & 31, w = t >> 5;
    const int qr = lane >> 2, qc = lane & 3;
    const int grp = lane >> 3, row = lane & 7;
    const int q0 = blockIdx.x * 128;
    const int bh = blockIdx.y;
    const int b = bh / HH, h = bh % HH;
    const __half* qb = qg + (long)b * NN * QLD + h * YY;
    const __half* kb = kg + (long)b * NN * QLD + h * YY;
    __half* dqb = dqg + (long)b * NN * QLD + h * YY;

    const uint32_t Qsu = smem_u32(Qs);
    const uint32_t Kau[2] = { smem_u32(Ka[0]), smem_u32(Ka[1]) };

    const uint32_t qoff = (uint32_t)(((w * 16 + ((grp & 1) << 3) + row) * QP
                                    + ((grp >> 1) << 3)) * 2);
    uint32_t soff[4], toff[4];
#pragma unroll
    for (int p = 0; p < 4; p++) {
        soff[p] = (uint32_t)((((2 * p + (grp >> 1)) * 8 + row) * QP
                             + ((grp & 1) << 3)) * 2);
        toff[p] = (uint32_t)(((((grp & 1) << 3) + row) * QP
                             + (2 * p + (grp >> 1)) * 8) * 2);
    }

#pragma unroll
    for (int p = 0; p < 4; p++) {
        int c = t + p * 256;
        int i = c >> 3, jc = c & 7;
        cp_async16(Qsu + (uint32_t)(i * QP + 8 * jc) * 2,
                   qb + (long)(q0 + i) * QLD + 8 * jc);
    }
#pragma unroll
    for (int p = 0; p < 2; p++) {
        int c = t + p * 256;
        int i = c >> 3, jc = c & 7;
        cp_async16(Kau[0] + (uint32_t)(i * QP + 8 * jc) * 2,
                   kb + (long)i * QLD + 8 * jc);
    }
    CP_COMMIT();

    float m0 = -1e30f, m1 = -1e30f, l0 = 0.f, l1 = 0.f;
    float dqa[8][4];
#pragma unroll
    for (int i = 0; i < 8; i++)
#pragma unroll
        for (int e = 0; e < 4; e++) dqa[i][e] = 0.f;

    for (int c = 0; c < 16; c++) {
        const int buf = c & 1;
        if (c + 1 < 16) {
#pragma unroll
            for (int p = 0; p < 2; p++) {
                int cc = t + p * 256;
                int i = cc >> 3, jc = cc & 7;
                cp_async16(Kau[buf ^ 1] + (uint32_t)(i * QP + 8 * jc) * 2,
                           kb + (long)((c + 1) * 64 + i) * QLD + 8 * jc);
            }
        }
        CP_COMMIT();
        CP_WAIT1();
        __syncthreads();

        float s[8][4];
#pragma unroll
        for (int i = 0; i < 8; i++)
#pragma unroll
            for (int e = 0; e < 4; e++) s[i][e] = 0.f;
#pragma unroll
        for (int kc = 0; kc < 4; kc++) {
            uint32_t a[4], bf[8][2];
            ldsm_x4(a[0], a[1], a[2], a[3], Qsu + qoff + kc * 32);
#pragma unroll
            for (int p = 0; p < 4; p++)
                ldsm_x4(bf[2 * p][0], bf[2 * p][1], bf[2 * p + 1][0], bf[2 * p + 1][1],
                        Kau[buf] + soff[p] + kc * 32);
#pragma unroll
            for (int nt = 0; nt < 8; nt++)
                mma_fp16(s[nt], a, bf[nt]);
        }
#pragma unroll
        for (int nt = 0; nt < 8; nt++)
#pragma unroll
            for (int e = 0; e < 4; e++) s[nt][e] *= BETA_ATT;

        float bm0 = -1e30f, bm1 = -1e30f;
#pragma unroll
        for (int nt = 0; nt < 8; nt++) {
            bm0 = fmaxf(bm0, fmaxf(s[nt][0], s[nt][1]));
            bm1 = fmaxf(bm1, fmaxf(s[nt][2], s[nt][3]));
        }
        bm0 = fmaxf(bm0, __shfl_xor_sync(0xffffffffu, bm0, 1));
        bm0 = fmaxf(bm0, __shfl_xor_sync(0xffffffffu, bm0, 2));
        bm1 = fmaxf(bm1, __shfl_xor_sync(0xffffffffu, bm1, 1));
        bm1 = fmaxf(bm1, __shfl_xor_sync(0xffffffffu, bm1, 2));
        float mn0 = fmaxf(m0, bm0), mn1 = fmaxf(m1, bm1);
        float rs0 = __expf(m0 - mn0), rs1 = __expf(m1 - mn1);
        m0 = mn0; m1 = mn1;

        uint32_t Pf[8][2];
        float lp0 = 0.f, lp1 = 0.f;
#pragma unroll
        for (int nt = 0; nt < 8; nt++) {
            float p0 = __expf(s[nt][0] - m0), p1 = __expf(s[nt][1] - m0);
            float p2 = __expf(s[nt][2] - m1), p3 = __expf(s[nt][3] - m1);
            lp0 += p0 + p1; lp1 += p2 + p3;
            __half2 x = __floats2half2_rn(p0, p1); Pf[nt][0] = *(uint32_t*)&x;
            __half2 y = __floats2half2_rn(p2, p3); Pf[nt][1] = *(uint32_t*)&y;
        }
        l0 = l0 * rs0 + lp0; l1 = l1 * rs1 + lp1;
#pragma unroll
        for (int nt = 0; nt < 8; nt++) {
            dqa[nt][0] *= rs0; dqa[nt][1] *= rs0;
            dqa[nt][2] *= rs1; dqa[nt][3] *= rs1;
        }

#pragma unroll
        for (int kc = 0; kc < 4; kc++) {
            uint32_t a[4] = { Pf[2 * kc][0], Pf[2 * kc][1],
                              Pf[2 * kc + 1][0], Pf[2 * kc + 1][1] };
            uint32_t bf[8][2];
#pragma unroll
            for (int p = 0; p < 4; p++)
                ldsm_x4_t(bf[2 * p][0], bf[2 * p][1], bf[2 * p + 1][0], bf[2 * p + 1][1],
                          Kau[buf] + toff[p] + (uint32_t)(kc * 16 * QP * 2));
#pragma unroll
            for (int nt = 0; nt < 8; nt++)
                mma_fp16(dqa[nt], a, bf[nt]);
        }
        __syncthreads();
    }

    l0 += __shfl_xor_sync(0xffffffffu, l0, 1);
    l0 += __shfl_xor_sync(0xffffffffu, l0, 2);
    l1 += __shfl_xor_sync(0xffffffffu, l1, 1);
    l1 += __shfl_xor_sync(0xffffffffu, l1, 2);
    const float li0 = 1.f / l0, li1 = 1.f / l1;

    const int r0 = q0 + w * 16 + qr;
#pragma unroll
    for (int nt = 0; nt < 8; nt++) {
        int col = nt * 8 + 2 * qc;
        __half2 v0 = __floats2half2_rn(dqa[nt][0] * li0, dqa[nt][1] * li0);
        __half2 v1 = __floats2half2_rn(dqa[nt][2] * li1, dqa[nt][3] * li1);
        *(uint32_t*)(dqb + (long)r0 * QLD + col) = *(uint32_t*)&v0;
        *(uint32_t*)(dqb + (long)(r0 + 8) * QLD + col) = *(uint32_t*)&v1;
    }
    if (qc == 0) {
        lse[(long)bh * NN + r0]     = m0 + logf(l0);
        lse[(long)bh * NN + r0 + 8] = m1 + logf(l1);
    }
}

__global__ __launch_bounds__(256, 2)
void dk_flash(const __half* __restrict__ qg, const __half* __restrict__ kg,
              __half* __restrict__ dkg, const float* __restrict__ lse)
{
    __shared__ __half Ks[128 * QP];
    __shared__ __half Qa[2][64 * QP];
    __shared__ float sL[64];

    const int t = threadIdx.x, lane = t & 31, w = t >> 5;
    const int qr = lane >> 2, qc = lane & 3;
    const int grp = lane >> 3, row = lane & 7;
    const int k0 = blockIdx.x * 128;
    const int bh = blockIdx.y;
    const int b = bh / HH, h = bh % HH;
    const __half* qb = qg + (long)b * NN * QLD + h * YY;
    const __half* kb = kg + (long)b * NN * QLD + h * YY;
    __half* dkb = dkg + (long)b * NN * QLD + h * YY;

    const uint32_t Ksu = smem_u32(Ks);
    const uint32_t Qau[2] = { smem_u32(Qa[0]), smem_u32(Qa[1]) };

    const uint32_t koff = (uint32_t)(((w * 16 + ((grp & 1) << 3) + row) * QP
                                    + ((grp >> 1) << 3)) * 2);
    uint32_t soff[4], toff[4];
#pragma unroll
    for (int p = 0; p < 4; p++) {
        soff[p] = (uint32_t)((((2 * p + (grp >> 1)) * 8 + row) * QP
                             + ((grp & 1) << 3)) * 2);
        toff[p] = (uint32_t)(((((grp & 1) << 3) + row) * QP
                             + (2 * p + (grp >> 1)) * 8) * 2);
    }

#pragma unroll
    for (int p = 0; p < 4; p++) {
        int c = t + p * 256;
        int i = c >> 3, jc = c & 7;
        cp_async16(Ksu + (uint32_t)(i * QP + 8 * jc) * 2,
                   kb + (long)(k0 + i) * QLD + 8 * jc);
    }
#pragma unroll
    for (int p = 0; p < 2; p++) {
        int c = t + p * 256;
        int i = c >> 3, jc = c & 7;
        cp_async16(Qau[0] + (uint32_t)(i * QP + 8 * jc) * 2,
                   qb + (long)i * QLD + 8 * jc);
    }
    CP_COMMIT();

    float dka[8][4];
#pragma unroll
    for (int i = 0; i < 8; i++)
#pragma unroll
        for (int e = 0; e < 4; e++) dka[i][e] = 0.f;

    float pl = (t < 64) ? lse[(long)bh * NN + t] : 0.f;

    for (int c = 0; c < 16; c++) {
        const int buf = c & 1;
        if (c + 1 < 16) {
#pragma unroll
            for (int p = 0; p < 2; p++) {
                int cc = t + p * 256;
                int i = cc >> 3, jc = cc & 7;
                cp_async16(Qau[buf ^ 1] + (uint32_t)(i * QP + 8 * jc) * 2,
                           qb + (long)((c + 1) * 64 + i) * QLD + 8 * jc);
            }
        }
        CP_COMMIT();
        CP_WAIT1();
        if (t < 64) sL[t] = pl;
        __syncthreads();
        if (c + 1 < 16 && t < 64) pl = lse[(long)bh * NN + (c + 1) * 64 + t];

        float s[8][4];
#pragma unroll
        for (int i = 0; i < 8; i++)
#pragma unroll
            for (int e = 0; e < 4; e++) s[i][e] = 0.f;
#pragma unroll
        for (int kc = 0; kc < 4; kc++) {
            uint32_t a[4], bf[8][2];
            ldsm_x4(a[0], a[1], a[2], a[3], Ksu + koff + kc * 32);
#pragma unroll
            for (int p = 0; p < 4; p++)
                ldsm_x4(bf[2 * p][0], bf[2 * p][1], bf[2 * p + 1][0], bf[2 * p + 1][1],
                        Qau[buf] + soff[p] + kc * 32);
#pragma unroll
            for (int nt = 0; nt < 8; nt++)
                mma_fp16(s[nt], a, bf[nt]);
        }

        uint32_t Pf[8][2];
#pragma unroll
        for (int nt = 0; nt < 8; nt++) {
            float ls0 = sL[nt * 8 + 2 * qc], ls1 = sL[nt * 8 + 2 * qc + 1];
            float p0 = __expf(s[nt][0] * BETA_ATT - ls0);
            float p1 = __expf(s[nt][1] * BETA_ATT - ls1);
            float p2 = __expf(s[nt][2] * BETA_ATT - ls0);
            float p3 = __expf(s[nt][3] * BETA_ATT - ls1);
            __half2 x = __floats2half2_rn(p0, p1); Pf[nt][0] = *(uint32_t*)&x;
            __half2 y = __floats2half2_rn(p2, p3); Pf[nt][1] = *(uint32_t*)&y;
        }
#pragma unroll
        for (int kc = 0; kc < 4; kc++) {
            uint32_t a[4] = { Pf[2 * kc][0], Pf[2 * kc][1],
                              Pf[2 * kc + 1][0], Pf[2 * kc + 1][1] };
            uint32_t bf[8][2];
#pragma unroll
            for (int p = 0; p < 4; p++)
                ldsm_x4_t(bf[2 * p][0], bf[2 * p][1], bf[2 * p + 1][0], bf[2 * p + 1][1],
                          Qau[buf] + toff[p] + (uint32_t)(kc * 16 * QP * 2));
#pragma unroll
            for (int nt = 0; nt < 8; nt++)
                mma_fp16(dka[nt], a, bf[nt]);
        }
        __syncthreads();
    }

    const int r0 = k0 + w * 16 + qr;
#pragma unroll
    for (int nt = 0; nt < 8; nt++) {
        int col = nt * 8 + 2 * qc;
        __half2 v0 = __floats2half2_rn(dka[nt][0], dka[nt][1]);
        __half2 v1 = __floats2half2_rn(dka[nt][2], dka[nt][3]);
        *(uint32_t*)(dkb + (long)r0 * QLD + col) = *(uint32_t*)&v0;
        *(uint32_t*)(dkb + (long)(r0 + 8) * QLD + col) = *(uint32_t*)&v1;
    }
}

// ===========================================================================
// LayerNorm (fp32 in, fp16 out); fused x-update variant
// ===========================================================================
template<int UPD>
__global__ __launch_bounds__(256)
void ln_kernel(float* __restrict__ x, const float* __restrict__ acc,
               const float* __restrict__ gamma, const float* __restrict__ beta,
               __half* __restrict__ g)
{
    const long base = (long)blockIdx.x * DD;
    const int t = threadIdx.x;
    float v[3];
    float s = 0.f, ss = 0.f;
#pragma unroll
    for (int i = 0; i < 3; i++) {
        long idx = base + t + i * 256;
        float xv = x[idx];
        if (UPD) { xv = fmaf(ALPHA, acc[idx], xv); x[idx] = xv; }
        v[i] = xv;
        s += xv;
        ss = fmaf(xv, xv, ss);
    }
#pragma unroll
    for (int o = 16; o > 0; o >>= 1) {
        s  += __shfl_xor_sync(0xffffffffu, s, o);
        ss += __shfl_xor_sync(0xffffffffu, ss, o);
    }
    __shared__ float rs[8], rss[8], bc[2];
    if ((t & 31) == 0) { rs[t >> 5] = s; rss[t >> 5] = ss; }
    __syncthreads();
    if (t == 0) {
        float a = 0.f, bsum = 0.f;
#pragma unroll
        for (int i = 0; i < 8; i++) { a += rs[i]; bsum += rss[i]; }
        float mean = a * (1.f / DD);
        float var  = bsum * (1.f / DD) - mean * mean;
        bc[0] = mean;
        bc[1] = rsqrtf(var + EPS_LN);
    }
    __syncthreads();
    const float mean = bc[0], rinv = bc[1];
#pragma unroll
    for (int i = 0; i < 3; i++) {
        int col = t + i * 256;
        g[base + col] = __float2half(gamma[col] * (v[i] - mean) * rinv + beta[col]);
    }
}

__global__ __launch_bounds__(256)
void update_kernel(float* __restrict__ x, const float* __restrict__ acc)
{
    long i = (long)blockIdx.x * 256 + threadIdx.x;
    x[i] = fmaf(ALPHA, acc[i], x[i]);
}

// Build concatenated projection weights: wqkh [1536][768], wT2 [768][1536]
__global__ __launch_bounds__(256)
void prep_qk(const float* __restrict__ Wq, const float* __restrict__ Wk,
             __half* __restrict__ wqkh, __half* __restrict__ wT2)
{
    int i = blockIdx.x * 256 + threadIdx.x;
    if (i < DD * DD) {
        int r = i / DD, c = i % DD;
        __half hq = __float2half(Wq[i]);
        __half hk = __float2half(Wk[i]);
        wqkh[i] = hq;
        wqkh[(long)(DD + r) * DD + c] = hk;
        wT2[(long)c * QLD + r] = hq;
        wT2[(long)c * QLD + DD + r] = hk;
    }
}

__global__ __launch_bounds__(256)
void prep_xi(const float* __restrict__ X, __half* __restrict__ Xh,
             __half* __restrict__ XT)
{
    int i = blockIdx.x * 256 + threadIdx.x;
    if (i < MM * DD) {
        int r = i / DD, c = i % DD;
        __half h = __float2half(X[i]);
        Xh[i] = h;
        XT[(long)c * MM + r] = h;
    }
}

// ===========================================================================
// Host
// ===========================================================================
static const int SMEMH = 3 * 2 * 128 * HP * 2;   // 110592 bytes (3 stages)

template<int OH>
static void hc(const __half* A, const __half* B, void* C, int M, int N, int K,
               long lda, long ldb, long ldc, float scale, int relu, int accum)
{
    cudaFuncSetAttribute(hgemm<OH>, cudaFuncAttributeMaxDynamicSharedMemorySize, SMEMH);
    dim3 grid(N / 128, M / 128, 1);
    hgemm<OH><<<grid, 256, SMEMH>>>(A, B, C, K, lda, ldb, ldc, scale, relu, accum);
}

extern "C" void kernel_launch(void* const* d_in, const int* in_sizes, int n_in,
                              void* d_out, int out_size)
{
    const float* x_in  = (const float*)d_in[0];
    const float* gamma = (const float*)d_in[1];
    const float* betaL = (const float*)d_in[2];
    const float* Wq    = (const float*)d_in[3];
    const float* Wk    = (const float*)d_in[4];
    const float* xi    = (const float*)d_in[5];

    float* xb = (float*)d_out;

    __half *g, *qk, *dqk, *r, *wqkh, *wT2, *xih, *xiT;
    float *acc, *lse;
    cudaGetSymbolAddress((void**)&g,    d_g);
    cudaGetSymbolAddress((void**)&qk,   d_qk);
    cudaGetSymbolAddress((void**)&dqk,  d_dqk);
    cudaGetSymbolAddress((void**)&r,    d_r);
    cudaGetSymbolAddress((void**)&acc,  d_acc);
    cudaGetSymbolAddress((void**)&lse,  d_lse);
    cudaGetSymbolAddress((void**)&wqkh, d_wqkh);
    cudaGetSymbolAddress((void**)&wT2,  d_wT2);
    cudaGetSymbolAddress((void**)&xih,  d_xih);
    cudaGetSymbolAddress((void**)&xiT,  d_xiT);

    cudaMemcpyAsync(xb, x_in, (size_t)GSZ * sizeof(float), cudaMemcpyDeviceToDevice, 0);

    prep_qk<<<(DD * DD + 255) / 256, 256>>>(Wq, Wk, wqkh, wT2);
    prep_xi<<<(MM * DD + 255) / 256, 256>>>(xi, xih, xiT);

    ln_kernel<0><<<BN_TOK, 256>>>(xb, acc, gamma, betaL, g);

    for (int step = 0; step < STEPS; step++) {
        // qk = g @ [Wq;Wk]^T   one GEMM, N=1536
        hc<1>(g, wqkh, qk, BN_TOK, QLD, DD, DD, DD, QLD, 1.f, 0, 0);

        // Flash attention gradients (q = qk col 0, k = qk col 768)
        dq_flash<<<dim3(NN / 128, BB * HH), 256>>>(qk, qk + DD, dqk, lse);
        dk_flash<<<dim3(NN / 128, BB * HH), 256>>>(qk, qk + DD, dqk + DD, lse);

        // acc = [dq|dk] @ [Wq;Wk]   one GEMM, K=1536 (no accumulate pass)
        hc<0>(dqk, wT2, acc, BN_TOK, DD, QLD, QLD, QLD, DD, 1.f, 0, 0);

        // r = relu(g @ xi^T) ; acc += r @ xi
        hc<1>(g, xih, r, BN_TOK, MM, DD, DD, DD, MM, 1.f, 1, 0);
        hc<0>(r, xiT, acc, BN_TOK, DD, MM, MM, MM, DD, 1.f, 0, 1);

        // fused x-update + next-step layernorm (plain update on last step)
        if (step + 1 < STEPS)
            ln_kernel<1><<<BN_TOK, 256>>>(xb, acc, gamma, betaL, g);
        else
            update_kernel<<<GSZ / 256, 256>>>(xb, acc);
    }
}